// round 5
// baseline (speedup 1.0000x reference)
#include <cuda_runtime.h>
#include <math.h>

// ---- problem constants (hardcoded; shapes fixed by the dataset) ----
#define Bq   4
#define Sq   2048
#define Dq   1024
#define Hq   4
#define HDq  256
#define ROWSq (Bq*Sq)          // 8192
#define SCORE_ELEMS ((size_t)Bq*Hq*Sq*Sq)   // 67108864

// ---- device scratch (allocation-free: static device globals) ----
__device__ float g_Q [ROWSq*Dq];
__device__ float g_K [ROWSq*Dq];
__device__ float g_V [ROWSq*Dq];
__device__ float g_O [ROWSq*Dq];   // attention output (pre-blend)
__device__ float g_BL[ROWSq*Dq];   // blended output (pre out-proj)
__device__ float g_SK[ROWSq*Dq];   // elu(K)+1
__device__ float g_VP[ROWSq*Dq];   // v - delta
__device__ float g_S [SCORE_ELEMS];// score / prob matrices, 16 x 2048 x 2048

#define TS 68   // smem tile row stride in floats (64 + pad, 16B-aligned)

// 4x4-per-thread microkernel over a 16-deep k-slice held in smem (As/Bs are
// [k][m]/[k][n] with stride TS).
__device__ __forceinline__ void micro16(const float (*As)[TS], const float (*Bs)[TS],
                                        int tx, int ty, float acc[4][4]) {
#pragma unroll
    for (int kk = 0; kk < 16; kk++) {
        float4 a = *(const float4*)&As[kk][ty*4];
        float4 b = *(const float4*)&Bs[kk][tx*4];
        acc[0][0] += a.x*b.x; acc[0][1] += a.x*b.y; acc[0][2] += a.x*b.z; acc[0][3] += a.x*b.w;
        acc[1][0] += a.y*b.x; acc[1][1] += a.y*b.y; acc[1][2] += a.y*b.z; acc[1][3] += a.y*b.w;
        acc[2][0] += a.z*b.x; acc[2][1] += a.z*b.y; acc[2][2] += a.z*b.z; acc[2][3] += a.z*b.w;
        acc[3][0] += a.w*b.x; acc[3][1] += a.w*b.y; acc[3][2] += a.w*b.z; acc[3][3] += a.w*b.w;
    }
}

// ---------------------------------------------------------------------------
// C = A * B^T  (A: [M,K] row-major, B: [N,K] row-major). 64x64 tiles, BK=16.
// Batched via blockIdx.z: z -> (b = z>>2, h = z&3) offsets via two strides.
// causal: skip blocks with bn > bm (for S = Q K^T scores).
// ---------------------------------------------------------------------------
__global__ void __launch_bounds__(256) gemm_nt(
    const float* __restrict__ A, const float* __restrict__ Bm,
    float* __restrict__ C, const float* __restrict__ bias,
    int K, int lda, int ldb, int ldc,
    long aSB, long aSH, long bSB, long bSH, long cSB, long cSH,
    int causal)
{
    int z = blockIdx.z;
    A  += (long)(z>>2)*aSB + (long)(z&3)*aSH;
    Bm += (long)(z>>2)*bSB + (long)(z&3)*bSH;
    C  += (long)(z>>2)*cSB + (long)(z&3)*cSH;
    int bm = blockIdx.y, bn = blockIdx.x;
    if (causal && bn > bm) return;

    __shared__ float As[16][TS], Bs[16][TS];
    int tid = threadIdx.x;
    int tx = tid & 15, ty = tid >> 4;
    int lr = tid >> 2, lf = tid & 3;      // 64 rows x 4 float4's of k

    const float* aP = A  + (long)(bm*64 + lr)*lda + lf*4;
    const float* bP = Bm + (long)(bn*64 + lr)*ldb + lf*4;

    float acc[4][4] = {};
    for (int k0 = 0; k0 < K; k0 += 16) {
        float4 av = *(const float4*)(aP + k0);
        float4 bv = *(const float4*)(bP + k0);
        __syncthreads();
        As[lf*4+0][lr]=av.x; As[lf*4+1][lr]=av.y; As[lf*4+2][lr]=av.z; As[lf*4+3][lr]=av.w;
        Bs[lf*4+0][lr]=bv.x; Bs[lf*4+1][lr]=bv.y; Bs[lf*4+2][lr]=bv.z; Bs[lf*4+3][lr]=bv.w;
        __syncthreads();
        micro16(As, Bs, tx, ty, acc);
    }

#pragma unroll
    for (int i = 0; i < 4; i++) {
        long row = bm*64 + ty*4 + i;
        int  col = bn*64 + tx*4;
        float4 o = make_float4(acc[i][0], acc[i][1], acc[i][2], acc[i][3]);
        if (bias) { o.x += bias[col]; o.y += bias[col+1]; o.z += bias[col+2]; o.w += bias[col+3]; }
        *(float4*)&C[row*ldc + col] = o;
    }
}

// ---------------------------------------------------------------------------
// C = A * B  (A: [M,K] row-major, B: [K,N] row-major). For O = P @ V.
// causalTrim: k-loop stops at (bm+1)*64 (P is exactly zero above the diagonal).
// ---------------------------------------------------------------------------
__global__ void __launch_bounds__(256) gemm_nn(
    const float* __restrict__ A, const float* __restrict__ Bm,
    float* __restrict__ C,
    int K, int lda, int ldb, int ldc,
    long aSB, long aSH, long bSB, long bSH, long cSB, long cSH,
    int causalTrim)
{
    int z = blockIdx.z;
    A  += (long)(z>>2)*aSB + (long)(z&3)*aSH;
    Bm += (long)(z>>2)*bSB + (long)(z&3)*bSH;
    C  += (long)(z>>2)*cSB + (long)(z&3)*cSH;
    int bm = blockIdx.y, bn = blockIdx.x;
    int kEnd = causalTrim ? min(K, (bm+1)*64) : K;

    __shared__ float As[16][TS], Bs[16][TS];
    int tid = threadIdx.x;
    int tx = tid & 15, ty = tid >> 4;
    int lr  = tid >> 2, lf = tid & 3;     // A loads (transpose to [k][m])
    int bkr = tid >> 4, bf = tid & 15;    // B loads (direct [k][n])

    const float* aP = A  + (long)(bm*64 + lr)*lda + lf*4;
    const float* bP = Bm + (long)bkr*ldb + bn*64 + bf*4;

    float acc[4][4] = {};
    for (int k0 = 0; k0 < kEnd; k0 += 16) {
        float4 av = *(const float4*)(aP + k0);
        float4 bv = *(const float4*)(bP + (long)k0*ldb);
        __syncthreads();
        As[lf*4+0][lr]=av.x; As[lf*4+1][lr]=av.y; As[lf*4+2][lr]=av.z; As[lf*4+3][lr]=av.w;
        *(float4*)&Bs[bkr][bf*4] = bv;
        __syncthreads();
        micro16(As, Bs, tx, ty, acc);
    }

#pragma unroll
    for (int i = 0; i < 4; i++) {
        long row = bm*64 + ty*4 + i;
        int  col = bn*64 + tx*4;
        *(float4*)&C[row*ldc + col] =
            make_float4(acc[i][0], acc[i][1], acc[i][2], acc[i][3]);
    }
}

// ---------------------------------------------------------------------------
// mem_new[h] += (1/B) * SK_h^T @ VP_h  (both [8192, 256] slices of [8192,1024]).
// K split into 8 chunks of 1024 rows; partials land via atomicAdd (C was
// pre-initialized with mem by init_state).  z = h*8 + chunk.
// ---------------------------------------------------------------------------
__global__ void __launch_bounds__(256) gemm_tn_mem(
    const float* __restrict__ SKb, const float* __restrict__ VPb,
    float* __restrict__ Cout)
{
    int z = blockIdx.z;
    int h = z >> 3, ch = z & 7;
    const float* A  = SKb + h*HDq;     // A[k][m], lda = 1024
    const float* Bm = VPb + h*HDq;
    float* C = Cout + h*HDq*HDq;
    int bm = blockIdx.y, bn = blockIdx.x;
    int k0s = ch*1024, k0e = k0s + 1024;

    __shared__ float As[16][TS], Bs[16][TS];
    int tid = threadIdx.x;
    int tx = tid & 15, ty = tid >> 4;
    int kr = tid >> 4, f = tid & 15;

    const float* aP = A  + (long)kr*Dq + bm*64 + f*4;
    const float* bP = Bm + (long)kr*Dq + bn*64 + f*4;

    float acc[4][4] = {};
    for (int k0 = k0s; k0 < k0e; k0 += 16) {
        float4 av = *(const float4*)(aP + (long)k0*Dq);
        float4 bv = *(const float4*)(bP + (long)k0*Dq);
        __syncthreads();
        *(float4*)&As[kr][f*4] = av;
        *(float4*)&Bs[kr][f*4] = bv;
        __syncthreads();
        micro16(As, Bs, tx, ty, acc);
    }

#pragma unroll
    for (int i = 0; i < 4; i++)
#pragma unroll
        for (int j = 0; j < 4; j++)
            atomicAdd(&C[(bm*64 + ty*4 + i)*HDq + bn*64 + tx*4 + j], 0.25f*acc[i][j]);
}

// ---------------------------------------------------------------------------
// Causal softmax over one score row (no 1/sqrt(d) scaling, faithful to ref).
// Valid columns: [0, i]; columns (i, S) are written as exact zeros.
// ---------------------------------------------------------------------------
__global__ void __launch_bounds__(256) softmax_causal(float* __restrict__ Sb)
{
    int row = blockIdx.x;                 // 0..32767
    int bh = row >> 11, i = row & 2047;
    float* p = Sb + (size_t)bh*Sq*Sq + (size_t)i*Sq;
    int n = i + 1;
    int tid = threadIdx.x;
    __shared__ float red[8];

    float m = -3.0e38f;
    for (int j = tid; j < n; j += 256) m = fmaxf(m, p[j]);
#pragma unroll
    for (int o = 16; o > 0; o >>= 1) m = fmaxf(m, __shfl_xor_sync(0xffffffffu, m, o));
    if ((tid & 31) == 0) red[tid >> 5] = m;
    __syncthreads();
    m = red[0];
#pragma unroll
    for (int w = 1; w < 8; w++) m = fmaxf(m, red[w]);
    __syncthreads();

    float s = 0.f;
    for (int j = tid; j < n; j += 256) { float e = __expf(p[j] - m); p[j] = e; s += e; }
#pragma unroll
    for (int o = 16; o > 0; o >>= 1) s += __shfl_xor_sync(0xffffffffu, s, o);
    if ((tid & 31) == 0) red[tid >> 5] = s;
    __syncthreads();
    s = red[0] + red[1] + red[2] + red[3] + red[4] + red[5] + red[6] + red[7];

    float inv = 1.f / s;
    for (int j = tid; j < n; j += 256) p[j] *= inv;
    for (int j = n + tid; j < Sq; j += 256) p[j] = 0.f;
}

// ---------------------------------------------------------------------------
// A_mem / delta path.  For a 16-row x 1-head tile:
//   s  = elu(src)+1  (= x+1 if x>0 else exp(x))
//   num = s @ mem[h]        den = s . z[h] + 1e-6
// mode 0 (blend):  out = g*num/den + (1-g)*attn       (aux = g_O)
// mode 1 (delta):  out = v - num/den; also store s -> skout  (aux = g_V)
// ---------------------------------------------------------------------------
__global__ void __launch_bounds__(256) amem_kernel(
    const float* __restrict__ src, const float* __restrict__ aux,
    const float* __restrict__ mem, const float* __restrict__ zv,
    const float* __restrict__ betas,
    float* __restrict__ outp, float* __restrict__ skout, int mode)
{
    __shared__ float sq[16][260];
    __shared__ float zh[256];
    __shared__ float den[16];
    __shared__ float red[8];

    int h = blockIdx.y;
    long row0 = (long)blockIdx.x * 16;
    int tid = threadIdx.x;
    zh[tid] = zv[h*256 + tid];

#pragma unroll
    for (int r = 0; r < 16; r++) {
        long idx = (row0 + r)*Dq + h*256 + tid;
        float x = src[idx];
        float s = x > 0.f ? x + 1.f : __expf(x);
        sq[r][tid] = s;
        if (mode == 1) skout[idx] = s;
    }
    __syncthreads();

    for (int r = 0; r < 16; r++) {
        float v = sq[r][tid] * zh[tid];
#pragma unroll
        for (int o = 16; o > 0; o >>= 1) v += __shfl_xor_sync(0xffffffffu, v, o);
        if ((tid & 31) == 0) red[tid >> 5] = v;
        __syncthreads();
        if (tid == 0) {
            float t = red[0]+red[1]+red[2]+red[3]+red[4]+red[5]+red[6]+red[7];
            den[r] = t + 1e-6f;
        }
        __syncthreads();
    }

    float acc[16] = {};
    const float* mh = mem + h*HDq*HDq;
    for (int d0 = 0; d0 < 256; d0 += 4) {
        float m0 = mh[(d0+0)*256 + tid];
        float m1 = mh[(d0+1)*256 + tid];
        float m2 = mh[(d0+2)*256 + tid];
        float m3 = mh[(d0+3)*256 + tid];
#pragma unroll
        for (int r = 0; r < 16; r++) {
            float4 sv = *(const float4*)&sq[r][d0];
            acc[r] += sv.x*m0 + sv.y*m1 + sv.z*m2 + sv.w*m3;
        }
    }

    if (mode == 0) {
        float g = 1.f / (1.f + __expf(-betas[h]));
        float og = 1.f - g;
#pragma unroll
        for (int r = 0; r < 16; r++) {
            long idx = (row0 + r)*Dq + h*256 + tid;
            outp[idx] = g*(acc[r]/den[r]) + og*aux[idx];
        }
    } else {
#pragma unroll
        for (int r = 0; r < 16; r++) {
            long idx = (row0 + r)*Dq + h*256 + tid;
            outp[idx] = aux[idx] - acc[r]/den[r];
        }
    }
}

// Copy mem -> d_out mem region, z -> d_out z region (before atomic updates).
__global__ void __launch_bounds__(256) init_state(
    const float* __restrict__ mem, const float* __restrict__ zv,
    float* __restrict__ out_mem, float* __restrict__ out_z)
{
    int i = blockIdx.x*256 + threadIdx.x;
    if (i < Hq*HDq*HDq) out_mem[i] = mem[i];
    if (i < Hq*HDq)     out_z[i]   = zv[i];
}

// z_new[h,d] += (1/B) * sum_rows SK[row, h*256+d]
__global__ void __launch_bounds__(256) zsum_kernel(
    const float* __restrict__ SKb, float* __restrict__ outz)
{
    int col = blockIdx.x*256 + threadIdx.x;   // 0..1023
    long r0 = (long)blockIdx.y * 512;
    float s = 0.f;
#pragma unroll 4
    for (int r = 0; r < 512; r++) s += SKb[(r0 + r)*Dq + col];
    atomicAdd(&outz[col], 0.25f*s);
}

// ---------------------------------------------------------------------------
extern "C" void kernel_launch(void* const* d_in, const int* in_sizes, int n_in,
                              void* d_out, int out_size)
{
    const float* X     = (const float*)d_in[0];
    const float* Wq    = (const float*)d_in[1];
    const float* Wk    = (const float*)d_in[2];
    const float* Wv    = (const float*)d_in[3];
    const float* Wo    = (const float*)d_in[4];
    const float* bo    = (const float*)d_in[5];
    const float* betas = (const float*)d_in[6];
    const float* mem   = (const float*)d_in[7];
    const float* zv    = (const float*)d_in[8];
    float* out = (float*)d_out;

    float *Q, *K, *V, *O, *BL, *SK, *VP, *Sc;
    cudaGetSymbolAddress((void**)&Q,  g_Q);
    cudaGetSymbolAddress((void**)&K,  g_K);
    cudaGetSymbolAddress((void**)&V,  g_V);
    cudaGetSymbolAddress((void**)&O,  g_O);
    cudaGetSymbolAddress((void**)&BL, g_BL);
    cudaGetSymbolAddress((void**)&SK, g_SK);
    cudaGetSymbolAddress((void**)&VP, g_VP);
    cudaGetSymbolAddress((void**)&Sc, g_S);

    const long OUT_MEM = (long)ROWSq*Dq;            // 8388608
    const long OUT_Z   = OUT_MEM + Hq*HDq*HDq;      // +262144

    dim3 thr(256);

    // 1-3. Q/K/V projections: [8192,1024] = X @ W^T
    gemm_nt<<<dim3(16,128,1), thr>>>(X, Wq, Q, nullptr, 1024, 1024,1024,1024,
                                     0,0, 0,0, 0,0, 0);
    gemm_nt<<<dim3(16,128,1), thr>>>(X, Wk, K, nullptr, 1024, 1024,1024,1024,
                                     0,0, 0,0, 0,0, 0);
    gemm_nt<<<dim3(16,128,1), thr>>>(X, Wv, V, nullptr, 1024, 1024,1024,1024,
                                     0,0, 0,0, 0,0, 0);

    // 4. scores: S[bh] = Q_bh @ K_bh^T (causal blocks only)
    gemm_nt<<<dim3(32,32,16), thr>>>(Q, K, Sc, nullptr, 256, 1024,1024,2048,
                                     2097152L,256L, 2097152L,256L,
                                     16777216L,4194304L, 1);

    // 5. causal softmax (writes exact zeros above diagonal)
    softmax_causal<<<32768, thr>>>(Sc);

    // 6. O[bh] = P_bh @ V_bh (k-loop trimmed by causality)
    gemm_nn<<<dim3(4,32,16), thr>>>(Sc, V, O, 2048, 2048,1024,1024,
                                    16777216L,4194304L, 2097152L,256L,
                                    2097152L,256L, 1);

    // 7. blend: BL = g*A_mem + (1-g)*O
    amem_kernel<<<dim3(512,4), thr>>>(Q, O, mem, zv, betas, BL, nullptr, 0);

    // 8. delta: VP = V - delta, SK = elu(K)+1
    amem_kernel<<<dim3(512,4), thr>>>(K, V, mem, zv, betas, VP, SK, 1);

    // 9. state init, then atomic accumulations
    init_state<<<1024, thr>>>(mem, zv, out + OUT_MEM, out + OUT_Z);
    gemm_tn_mem<<<dim3(4,4,32), thr>>>(SK, VP, out + OUT_MEM);
    zsum_kernel<<<dim3(4,16), thr>>>(SK, out + OUT_Z);

    // 10. output projection: out = BL @ Wo^T + bo
    gemm_nt<<<dim3(16,128,1), thr>>>(BL, Wo, out, bo, 1024, 1024,1024,1024,
                                     0,0, 0,0, 0,0, 0);
}

// round 6
// speedup vs baseline: 1.1389x; 1.1389x over previous
#include <cuda_runtime.h>
#include <math.h>

// ---- problem constants ----
#define Bq   4
#define Sq   2048
#define Dq   1024
#define Hq   4
#define HDq  256
#define ROWSq (Bq*Sq)          // 8192
#define SCORE_ELEMS ((size_t)Bq*Hq*Sq*Sq)   // 67108864

// ---- device scratch ----
__device__ float g_Q [ROWSq*Dq];
__device__ float g_K [ROWSq*Dq];
__device__ float g_V [ROWSq*Dq];
__device__ float g_O [ROWSq*Dq];
__device__ float g_BL[ROWSq*Dq];
__device__ float g_SK[ROWSq*Dq];
__device__ float g_VP[ROWSq*Dq];
__device__ float g_S [SCORE_ELEMS];

#define TSW 132   // 128 + 4 pad; row stride 528B = 33*16 -> float4-aligned

// 8x8-per-thread microkernel over a 16-deep k-slice (As/Bs are [k][m]/[k][n]).
__device__ __forceinline__ void micro16(const float (*As)[TSW], const float (*Bs)[TSW],
                                        int tx, int ty, float acc[8][8]) {
#pragma unroll
    for (int kk = 0; kk < 16; kk++) {
        float a[8], b[8];
        *(float4*)&a[0] = *(const float4*)&As[kk][ty*4];
        *(float4*)&a[4] = *(const float4*)&As[kk][ty*4+64];
        *(float4*)&b[0] = *(const float4*)&Bs[kk][tx*4];
        *(float4*)&b[4] = *(const float4*)&Bs[kk][tx*4+64];
#pragma unroll
        for (int i = 0; i < 8; i++)
#pragma unroll
            for (int j = 0; j < 8; j++)
                acc[i][j] += a[i]*b[j];
    }
}

// ---------------------------------------------------------------------------
// Shared NT body: C[128x128 tile] = A * B^T (+bias). A:[M,K], B:[N,K] row-major.
// ---------------------------------------------------------------------------
__device__ __forceinline__ void gemm_nt_body(
    const float* __restrict__ A, const float* __restrict__ Bm,
    float* __restrict__ C, const float* __restrict__ bias,
    int K, int lda, int ldb, int ldc, int bm, int bn)
{
    __shared__ float As[16][TSW], Bs[16][TSW];
    int tid = threadIdx.x;
    int tx = tid & 15, ty = tid >> 4;
    int r = tid >> 2, q = tid & 3;     // loader: 64 rows x 4 float4-of-k, x2 row halves

    const float* aP0 = A  + (long)(bm*128 + r)*lda + q*4;
    const float* aP1 = aP0 + (long)64*lda;
    const float* bP0 = Bm + (long)(bn*128 + r)*ldb + q*4;
    const float* bP1 = bP0 + (long)64*ldb;

    float acc[8][8] = {};
    float4 av0 = *(const float4*)(aP0);
    float4 av1 = *(const float4*)(aP1);
    float4 bv0 = *(const float4*)(bP0);
    float4 bv1 = *(const float4*)(bP1);

    for (int k0 = 0; k0 < K; k0 += 16) {
        __syncthreads();
        As[q*4+0][r]=av0.x; As[q*4+1][r]=av0.y; As[q*4+2][r]=av0.z; As[q*4+3][r]=av0.w;
        As[q*4+0][r+64]=av1.x; As[q*4+1][r+64]=av1.y; As[q*4+2][r+64]=av1.z; As[q*4+3][r+64]=av1.w;
        Bs[q*4+0][r]=bv0.x; Bs[q*4+1][r]=bv0.y; Bs[q*4+2][r]=bv0.z; Bs[q*4+3][r]=bv0.w;
        Bs[q*4+0][r+64]=bv1.x; Bs[q*4+1][r+64]=bv1.y; Bs[q*4+2][r+64]=bv1.z; Bs[q*4+3][r+64]=bv1.w;
        __syncthreads();
        if (k0 + 16 < K) {
            av0 = *(const float4*)(aP0 + k0 + 16);
            av1 = *(const float4*)(aP1 + k0 + 16);
            bv0 = *(const float4*)(bP0 + k0 + 16);
            bv1 = *(const float4*)(bP1 + k0 + 16);
        }
        micro16(As, Bs, tx, ty, acc);
    }

#pragma unroll
    for (int ii = 0; ii < 2; ii++)
#pragma unroll
        for (int i = 0; i < 4; i++) {
            long row = bm*128 + ii*64 + ty*4 + i;
            int  col = bn*128 + tx*4;
            float4 o0 = make_float4(acc[ii*4+i][0], acc[ii*4+i][1], acc[ii*4+i][2], acc[ii*4+i][3]);
            float4 o1 = make_float4(acc[ii*4+i][4], acc[ii*4+i][5], acc[ii*4+i][6], acc[ii*4+i][7]);
            if (bias) {
                o0.x += bias[col];    o0.y += bias[col+1];  o0.z += bias[col+2];  o0.w += bias[col+3];
                o1.x += bias[col+64]; o1.y += bias[col+65]; o1.z += bias[col+66]; o1.w += bias[col+67];
            }
            *(float4*)&C[row*ldc + col]      = o0;
            *(float4*)&C[row*ldc + col + 64] = o1;
        }
}

// generic batched NT (z -> (b,h) strides); causal skips bn > bm
__global__ void __launch_bounds__(256) gemm_nt(
    const float* __restrict__ A, const float* __restrict__ Bm,
    float* __restrict__ C, const float* __restrict__ bias,
    int K, int lda, int ldb, int ldc,
    long aSB, long aSH, long bSB, long bSH, long cSB, long cSH,
    int causal)
{
    int z = blockIdx.z;
    if (causal && blockIdx.x > blockIdx.y) return;
    gemm_nt_body(A + (long)(z>>2)*aSB + (long)(z&3)*aSH,
                 Bm + (long)(z>>2)*bSB + (long)(z&3)*bSH,
                 C + (long)(z>>2)*cSB + (long)(z&3)*cSH,
                 bias, K, lda, ldb, ldc, blockIdx.y, blockIdx.x);
}

// fused Q/K/V projections: z in {0,1,2} selects weight + destination
__global__ void __launch_bounds__(256) gemm_qkv(
    const float* __restrict__ X,
    const float* __restrict__ Wq, const float* __restrict__ Wk, const float* __restrict__ Wv,
    float* __restrict__ Q, float* __restrict__ K, float* __restrict__ V)
{
    int w = blockIdx.z;
    const float* Bm = (w == 0) ? Wq : (w == 1) ? Wk : Wv;
    float* C        = (w == 0) ? Q  : (w == 1) ? K  : V;
    gemm_nt_body(X, Bm, C, nullptr, 1024, 1024, 1024, 1024, blockIdx.y, blockIdx.x);
}

// ---------------------------------------------------------------------------
// C = A * B (NN).  For O = P @ V; k-loop trimmed to (bm+1)*128 by causality.
// ---------------------------------------------------------------------------
__global__ void __launch_bounds__(256) gemm_nn(
    const float* __restrict__ A, const float* __restrict__ Bm,
    float* __restrict__ C,
    int K, int lda, int ldb, int ldc,
    long aSB, long aSH, long bSB, long bSH, long cSB, long cSH,
    int causalTrim)
{
    int z = blockIdx.z;
    A  += (long)(z>>2)*aSB + (long)(z&3)*aSH;
    Bm += (long)(z>>2)*bSB + (long)(z&3)*bSH;
    C  += (long)(z>>2)*cSB + (long)(z&3)*cSH;
    int bm = blockIdx.y, bn = blockIdx.x;
    int kEnd = causalTrim ? min(K, (bm+1)*128) : K;

    __shared__ float As[16][TSW], Bs[16][TSW];
    int tid = threadIdx.x;
    int tx = tid & 15, ty = tid >> 4;
    int r  = tid >> 2, q  = tid & 3;    // A loads (transpose into [k][m])
    int kr = tid >> 4, nf = tid & 15;   // B loads (direct [k][n])

    const float* aP0 = A + (long)(bm*128 + r)*lda + q*4;
    const float* aP1 = aP0 + (long)64*lda;
    const float* bP  = Bm + (long)kr*ldb + bn*128 + nf*4;

    float acc[8][8] = {};
    float4 av0 = *(const float4*)(aP0);
    float4 av1 = *(const float4*)(aP1);
    float4 bv0 = *(const float4*)(bP);
    float4 bv1 = *(const float4*)(bP + 64);

    for (int k0 = 0; k0 < kEnd; k0 += 16) {
        __syncthreads();
        As[q*4+0][r]=av0.x; As[q*4+1][r]=av0.y; As[q*4+2][r]=av0.z; As[q*4+3][r]=av0.w;
        As[q*4+0][r+64]=av1.x; As[q*4+1][r+64]=av1.y; As[q*4+2][r+64]=av1.z; As[q*4+3][r+64]=av1.w;
        *(float4*)&Bs[kr][nf*4]    = bv0;
        *(float4*)&Bs[kr][nf*4+64] = bv1;
        __syncthreads();
        if (k0 + 16 < kEnd) {
            av0 = *(const float4*)(aP0 + k0 + 16);
            av1 = *(const float4*)(aP1 + k0 + 16);
            bv0 = *(const float4*)(bP + (long)(k0+16)*ldb);
            bv1 = *(const float4*)(bP + (long)(k0+16)*ldb + 64);
        }
        micro16(As, Bs, tx, ty, acc);
    }

#pragma unroll
    for (int ii = 0; ii < 2; ii++)
#pragma unroll
        for (int i = 0; i < 4; i++) {
            long row = bm*128 + ii*64 + ty*4 + i;
            int  col = bn*128 + tx*4;
            *(float4*)&C[row*ldc + col] =
                make_float4(acc[ii*4+i][0], acc[ii*4+i][1], acc[ii*4+i][2], acc[ii*4+i][3]);
            *(float4*)&C[row*ldc + col + 64] =
                make_float4(acc[ii*4+i][4], acc[ii*4+i][5], acc[ii*4+i][6], acc[ii*4+i][7]);
        }
}

// ---------------------------------------------------------------------------
// mem_new[h] += (1/B) * SK_h^T @ VP_h.  K=8192 split into 4 chunks of 2048;
// partials land via atomicAdd on the pre-initialized output.  z = h*4 + chunk.
// ---------------------------------------------------------------------------
__global__ void __launch_bounds__(256) gemm_tn_mem(
    const float* __restrict__ SKb, const float* __restrict__ VPb,
    float* __restrict__ Cout)
{
    int z = blockIdx.z;
    int h = z >> 2, ch = z & 3;
    const float* A  = SKb + h*HDq;   // [k][m], lda = 1024
    const float* Bm = VPb + h*HDq;
    float* C = Cout + h*HDq*HDq;
    int bm = blockIdx.y, bn = blockIdx.x;
    int k0s = ch*2048, k0e = k0s + 2048;

    __shared__ float As[16][TSW], Bs[16][TSW];
    int tid = threadIdx.x;
    int tx = tid & 15, ty = tid >> 4;
    int kr = tid >> 4, f = tid & 15;

    const float* aP = A  + (long)kr*Dq + bm*128 + f*4;
    const float* bP = Bm + (long)kr*Dq + bn*128 + f*4;

    float acc[8][8] = {};
    float4 av0 = *(const float4*)(aP + (long)k0s*Dq);
    float4 av1 = *(const float4*)(aP + (long)k0s*Dq + 64);
    float4 bv0 = *(const float4*)(bP + (long)k0s*Dq);
    float4 bv1 = *(const float4*)(bP + (long)k0s*Dq + 64);

    for (int k0 = k0s; k0 < k0e; k0 += 16) {
        __syncthreads();
        *(float4*)&As[kr][f*4]    = av0;
        *(float4*)&As[kr][f*4+64] = av1;
        *(float4*)&Bs[kr][f*4]    = bv0;
        *(float4*)&Bs[kr][f*4+64] = bv1;
        __syncthreads();
        if (k0 + 16 < k0e) {
            av0 = *(const float4*)(aP + (long)(k0+16)*Dq);
            av1 = *(const float4*)(aP + (long)(k0+16)*Dq + 64);
            bv0 = *(const float4*)(bP + (long)(k0+16)*Dq);
            bv1 = *(const float4*)(bP + (long)(k0+16)*Dq + 64);
        }
        micro16(As, Bs, tx, ty, acc);
    }

#pragma unroll
    for (int ii = 0; ii < 2; ii++)
#pragma unroll
        for (int i = 0; i < 4; i++) {
            int row = bm*128 + ii*64 + ty*4 + i;
#pragma unroll
            for (int jj = 0; jj < 2; jj++)
#pragma unroll
                for (int j = 0; j < 4; j++)
                    atomicAdd(&C[row*HDq + bn*128 + jj*64 + tx*4 + j],
                              0.25f*acc[ii*4+i][jj*4+j]);
        }
}

// ---------------------------------------------------------------------------
// Causal softmax over one score row. Valid cols [0,i]; (i,S) written as zeros.
// ---------------------------------------------------------------------------
__global__ void __launch_bounds__(256) softmax_causal(float* __restrict__ Sb)
{
    int row = blockIdx.x;
    int bh = row >> 11, i = row & 2047;
    float* p = Sb + (size_t)bh*Sq*Sq + (size_t)i*Sq;
    int n = i + 1;
    int tid = threadIdx.x;
    __shared__ float red[8];

    float m = -3.0e38f;
    for (int j = tid; j < n; j += 256) m = fmaxf(m, p[j]);
#pragma unroll
    for (int o = 16; o > 0; o >>= 1) m = fmaxf(m, __shfl_xor_sync(0xffffffffu, m, o));
    if ((tid & 31) == 0) red[tid >> 5] = m;
    __syncthreads();
    m = red[0];
#pragma unroll
    for (int w = 1; w < 8; w++) m = fmaxf(m, red[w]);
    __syncthreads();

    float s = 0.f;
    for (int j = tid; j < n; j += 256) { float e = __expf(p[j] - m); p[j] = e; s += e; }
#pragma unroll
    for (int o = 16; o > 0; o >>= 1) s += __shfl_xor_sync(0xffffffffu, s, o);
    if ((tid & 31) == 0) red[tid >> 5] = s;
    __syncthreads();
    s = red[0] + red[1] + red[2] + red[3] + red[4] + red[5] + red[6] + red[7];

    float inv = 1.f / s;
    for (int j = tid; j < n; j += 256) p[j] *= inv;
    for (int j = n + tid; j < Sq; j += 256) p[j] = 0.f;
}

// ---------------------------------------------------------------------------
// A_mem / delta path (unchanged from passing R5 version).
// ---------------------------------------------------------------------------
__global__ void __launch_bounds__(256) amem_kernel(
    const float* __restrict__ src, const float* __restrict__ aux,
    const float* __restrict__ mem, const float* __restrict__ zv,
    const float* __restrict__ betas,
    float* __restrict__ outp, float* __restrict__ skout, int mode)
{
    __shared__ float sq[16][260];
    __shared__ float zh[256];
    __shared__ float den[16];
    __shared__ float red[8];

    int h = blockIdx.y;
    long row0 = (long)blockIdx.x * 16;
    int tid = threadIdx.x;
    zh[tid] = zv[h*256 + tid];

#pragma unroll
    for (int r = 0; r < 16; r++) {
        long idx = (row0 + r)*Dq + h*256 + tid;
        float x = src[idx];
        float s = x > 0.f ? x + 1.f : __expf(x);
        sq[r][tid] = s;
        if (mode == 1) skout[idx] = s;
    }
    __syncthreads();

    for (int r = 0; r < 16; r++) {
        float v = sq[r][tid] * zh[tid];
#pragma unroll
        for (int o = 16; o > 0; o >>= 1) v += __shfl_xor_sync(0xffffffffu, v, o);
        if ((tid & 31) == 0) red[tid >> 5] = v;
        __syncthreads();
        if (tid == 0) {
            float t = red[0]+red[1]+red[2]+red[3]+red[4]+red[5]+red[6]+red[7];
            den[r] = t + 1e-6f;
        }
        __syncthreads();
    }

    float acc[16] = {};
    const float* mh = mem + h*HDq*HDq;
    for (int d0 = 0; d0 < 256; d0 += 4) {
        float m0 = mh[(d0+0)*256 + tid];
        float m1 = mh[(d0+1)*256 + tid];
        float m2 = mh[(d0+2)*256 + tid];
        float m3 = mh[(d0+3)*256 + tid];
#pragma unroll
        for (int r = 0; r < 16; r++) {
            float4 sv = *(const float4*)&sq[r][d0];
            acc[r] += sv.x*m0 + sv.y*m1 + sv.z*m2 + sv.w*m3;
        }
    }

    if (mode == 0) {
        float g = 1.f / (1.f + __expf(-betas[h]));
        float og = 1.f - g;
#pragma unroll
        for (int r = 0; r < 16; r++) {
            long idx = (row0 + r)*Dq + h*256 + tid;
            outp[idx] = g*(acc[r]/den[r]) + og*aux[idx];
        }
    } else {
#pragma unroll
        for (int r = 0; r < 16; r++) {
            long idx = (row0 + r)*Dq + h*256 + tid;
            outp[idx] = aux[idx] - acc[r]/den[r];
        }
    }
}

__global__ void __launch_bounds__(256) init_state(
    const float* __restrict__ mem, const float* __restrict__ zv,
    float* __restrict__ out_mem, float* __restrict__ out_z)
{
    int i = blockIdx.x*256 + threadIdx.x;
    if (i < Hq*HDq*HDq) out_mem[i] = mem[i];
    if (i < Hq*HDq)     out_z[i]   = zv[i];
}

__global__ void __launch_bounds__(256) zsum_kernel(
    const float* __restrict__ SKb, float* __restrict__ outz)
{
    int col = blockIdx.x*256 + threadIdx.x;
    long r0 = (long)blockIdx.y * 512;
    float s = 0.f;
#pragma unroll 4
    for (int r = 0; r < 512; r++) s += SKb[(r0 + r)*Dq + col];
    atomicAdd(&outz[col], 0.25f*s);
}

// ---------------------------------------------------------------------------
extern "C" void kernel_launch(void* const* d_in, const int* in_sizes, int n_in,
                              void* d_out, int out_size)
{
    const float* X     = (const float*)d_in[0];
    const float* Wq    = (const float*)d_in[1];
    const float* Wk    = (const float*)d_in[2];
    const float* Wv    = (const float*)d_in[3];
    const float* Wo    = (const float*)d_in[4];
    const float* bo    = (const float*)d_in[5];
    const float* betas = (const float*)d_in[6];
    const float* mem   = (const float*)d_in[7];
    const float* zv    = (const float*)d_in[8];
    float* out = (float*)d_out;

    float *Q, *K, *V, *O, *BL, *SK, *VP, *Sc;
    cudaGetSymbolAddress((void**)&Q,  g_Q);
    cudaGetSymbolAddress((void**)&K,  g_K);
    cudaGetSymbolAddress((void**)&V,  g_V);
    cudaGetSymbolAddress((void**)&O,  g_O);
    cudaGetSymbolAddress((void**)&BL, g_BL);
    cudaGetSymbolAddress((void**)&SK, g_SK);
    cudaGetSymbolAddress((void**)&VP, g_VP);
    cudaGetSymbolAddress((void**)&Sc, g_S);

    const long OUT_MEM = (long)ROWSq*Dq;
    const long OUT_Z   = OUT_MEM + Hq*HDq*HDq;

    dim3 thr(256);

    // 1. fused Q/K/V projections: [8192,1024] = X @ W^T  (z selects W, dest)
    gemm_qkv<<<dim3(8,64,3), thr>>>(X, Wq, Wk, Wv, Q, K, V);

    // 2. scores: S[bh] = Q_bh @ K_bh^T (causal blocks only)
    gemm_nt<<<dim3(16,16,16), thr>>>(Q, K, Sc, nullptr, 256, 1024,1024,2048,
                                     2097152L,256L, 2097152L,256L,
                                     16777216L,4194304L, 1);

    // 3. causal softmax (writes exact zeros above diagonal)
    softmax_causal<<<32768, thr>>>(Sc);

    // 4. O[bh] = P_bh @ V_bh (k-loop trimmed by causality)
    gemm_nn<<<dim3(2,16,16), thr>>>(Sc, V, O, 2048, 2048,1024,1024,
                                    16777216L,4194304L, 2097152L,256L,
                                    2097152L,256L, 1);

    // 5. blend: BL = g*A_mem + (1-g)*O
    amem_kernel<<<dim3(512,4), thr>>>(Q, O, mem, zv, betas, BL, nullptr, 0);

    // 6. delta: VP = V - delta, SK = elu(K)+1
    amem_kernel<<<dim3(512,4), thr>>>(K, V, mem, zv, betas, VP, SK, 1);

    // 7. state init, then accumulations
    init_state<<<1024, thr>>>(mem, zv, out + OUT_MEM, out + OUT_Z);
    gemm_tn_mem<<<dim3(2,2,16), thr>>>(SK, VP, out + OUT_MEM);
    zsum_kernel<<<dim3(4,16), thr>>>(SK, out + OUT_Z);

    // 8. output projection: out = BL @ Wo^T + bo
    gemm_nt<<<dim3(8,64,1), thr>>>(BL, Wo, out, bo, 1024, 1024,1024,1024,
                                   0,0, 0,0, 0,0, 0);
}

// round 8
// speedup vs baseline: 1.9503x; 1.7124x over previous
#include <cuda_runtime.h>
#include <cuda_bf16.h>
#include <math.h>
#include <stdint.h>

// ---- problem constants ----
#define Bq   4
#define Sq   2048
#define Dq   1024
#define Hq   4
#define HDq  256
#define ROWSq (Bq*Sq)          // 8192
#define SCORE_ELEMS ((size_t)Bq*Hq*Sq*Sq)   // 67108864

// ---- device scratch ----
__device__ float g_Q  [ROWSq*Dq];
__device__ float g_K  [ROWSq*Dq];
__device__ float g_V  [ROWSq*Dq];
__device__ float g_O  [ROWSq*Dq];
__device__ float g_BL [ROWSq*Dq];
__device__ float g_SK [ROWSq*Dq];
__device__ float g_VP [ROWSq*Dq];
__device__ float g_S  [SCORE_ELEMS];
__device__ float g_VT [16*HDq*Sq];      // V^T  per (b,h): [16][256][2048]
__device__ float g_SKT[Hq*HDq*ROWSq];   // SK^T per h:     [4][256][8192]
__device__ float g_VPT[Hq*HDq*ROWSq];   // VP^T per h

// ===========================================================================
// bf16x3 tensor-core NT GEMM:  C[128x128 tile] = A * B^T
// A:[M,K] row-major fp32, B:[N,K] row-major fp32, both k-contiguous.
// ===========================================================================
#define LDT 24           // bf16 row stride (16 data + 8 pad -> 48B, conflict-free)
#define STG (128*LDT)    // elems per (stage,sel) plane

__device__ __forceinline__ void ldsm4(uint32_t v[4], uint32_t addr) {
    asm volatile("ldmatrix.sync.aligned.m8n8.x4.shared.b16 {%0,%1,%2,%3}, [%4];"
                 : "=r"(v[0]), "=r"(v[1]), "=r"(v[2]), "=r"(v[3]) : "r"(addr));
}

__device__ __forceinline__ void mma16816(float c[4], const uint32_t a[4], const uint32_t b[2]) {
    asm volatile("mma.sync.aligned.m16n8k16.row.col.f32.bf16.bf16.f32 "
                 "{%0,%1,%2,%3},{%4,%5,%6,%7},{%8,%9},{%0,%1,%2,%3};"
                 : "+f"(c[0]), "+f"(c[1]), "+f"(c[2]), "+f"(c[3])
                 : "r"(a[0]), "r"(a[1]), "r"(a[2]), "r"(a[3]), "r"(b[0]), "r"(b[1]));
}

// split two floats into packed bf16 hi (returned) and bf16 lo (out param)
__device__ __forceinline__ uint32_t pack2(float x, float y, uint32_t &lo) {
    __nv_bfloat16 hx = __float2bfloat16(x);
    __nv_bfloat16 hy = __float2bfloat16(y);
    __nv_bfloat16 lx = __float2bfloat16(x - __bfloat162float(hx));
    __nv_bfloat16 ly = __float2bfloat16(y - __bfloat162float(hy));
    lo = (uint32_t)*(unsigned short*)&lx | ((uint32_t)*(unsigned short*)&ly << 16);
    return (uint32_t)*(unsigned short*)&hx | ((uint32_t)*(unsigned short*)&hy << 16);
}

// mode: 0 = plain store, 1 = +bias store, 2 = atomicAdd * 0.25f
__device__ __forceinline__ void gemm3_body(
    const float* __restrict__ A, const float* __restrict__ Bm,
    float* __restrict__ C, const float* __restrict__ bias,
    int kEnd, int lda, int ldb, int ldc, int bm, int bn, int mode)
{
    __shared__ __nv_bfloat16 As[2][2][128][LDT];   // [stage][hi/lo][m][k]
    __shared__ __nv_bfloat16 Bs[2][2][128][LDT];

    int tid  = threadIdx.x;
    int lane = tid & 31, wid = tid >> 5;
    int m0w = (wid >> 2) * 64;       // warp tile 64x32
    int n0w = (wid & 3) * 32;

    // ---- loaders: thread covers one (row, k-half) of the 128x16 slice ----
    int r = tid >> 1, half = tid & 1;
    const float* aG = A  + (long)(bm*128 + r)*lda + half*8;
    const float* bG = Bm + (long)(bn*128 + r)*ldb + half*8;

    uint32_t aBase = (uint32_t)__cvta_generic_to_shared(&As[0][0][0][0]);
    uint32_t bBase = (uint32_t)__cvta_generic_to_shared(&Bs[0][0][0][0]);

    // ldmatrix lane-derived offsets
    int g = lane >> 3, rr = lane & 7;
    int rA = (g & 1)*8 + rr,  kA = (g >> 1)*8;   // A quadrant order: mlo/klo, mhi/klo, mlo/khi, mhi/khi
    int rB = (g >> 1)*8 + rr, kB = (g & 1)*8;    // B quadrant order: nlo/klo, nlo/khi, nhi/klo, nhi/khi

    float acc[4][4][4];
#pragma unroll
    for (int i = 0; i < 4; i++)
#pragma unroll
        for (int j = 0; j < 4; j++)
#pragma unroll
            for (int q = 0; q < 4; q++) acc[i][j][q] = 0.f;

    float xa[8], xb[8];
    // prologue: load+split slice 0 into stage 0
    {
        float4 u0 = *(const float4*)(aG), u1 = *(const float4*)(aG + 4);
        float4 v0 = *(const float4*)(bG), v1 = *(const float4*)(bG + 4);
        xa[0]=u0.x; xa[1]=u0.y; xa[2]=u0.z; xa[3]=u0.w; xa[4]=u1.x; xa[5]=u1.y; xa[6]=u1.z; xa[7]=u1.w;
        xb[0]=v0.x; xb[1]=v0.y; xb[2]=v0.z; xb[3]=v0.w; xb[4]=v1.x; xb[5]=v1.y; xb[6]=v1.z; xb[7]=v1.w;
        uint32_t hA[4], lA[4], hB[4], lB[4];
#pragma unroll
        for (int p = 0; p < 4; p++) { hA[p] = pack2(xa[2*p], xa[2*p+1], lA[p]); hB[p] = pack2(xb[2*p], xb[2*p+1], lB[p]); }
        *(uint4*)&As[0][0][r][half*8] = make_uint4(hA[0],hA[1],hA[2],hA[3]);
        *(uint4*)&As[0][1][r][half*8] = make_uint4(lA[0],lA[1],lA[2],lA[3]);
        *(uint4*)&Bs[0][0][r][half*8] = make_uint4(hB[0],hB[1],hB[2],hB[3]);
        *(uint4*)&Bs[0][1][r][half*8] = make_uint4(lB[0],lB[1],lB[2],lB[3]);
    }
    __syncthreads();

    int nIter = kEnd >> 4;
    int st = 0;
    uint32_t a[4][4], b[4][2];

    for (int it = 0; it < nIter; ++it) {
        bool pf = (it + 1 < nIter);
        if (pf) {
            int k0 = (it + 1) * 16;
            float4 u0 = *(const float4*)(aG + k0), u1 = *(const float4*)(aG + k0 + 4);
            float4 v0 = *(const float4*)(bG + k0), v1 = *(const float4*)(bG + k0 + 4);
            xa[0]=u0.x; xa[1]=u0.y; xa[2]=u0.z; xa[3]=u0.w; xa[4]=u1.x; xa[5]=u1.y; xa[6]=u1.z; xa[7]=u1.w;
            xb[0]=v0.x; xb[1]=v0.y; xb[2]=v0.z; xb[3]=v0.w; xb[4]=v1.x; xb[5]=v1.y; xb[6]=v1.z; xb[7]=v1.w;
        }

        uint32_t aOffH = 2u*((uint32_t)(st*2+0)*STG + (uint32_t)(m0w + rA)*LDT + kA);
        uint32_t aOffL = 2u*((uint32_t)(st*2+1)*STG + (uint32_t)(m0w + rA)*LDT + kA);
        uint32_t bOffH = 2u*((uint32_t)(st*2+0)*STG + (uint32_t)(n0w + rB)*LDT + kB);
        uint32_t bOffL = 2u*((uint32_t)(st*2+1)*STG + (uint32_t)(n0w + rB)*LDT + kB);

        // pass 1: hi*hi
        {
            uint32_t t[4];
            ldsm4(t, bBase + bOffH);              b[0][0]=t[0]; b[0][1]=t[1]; b[1][0]=t[2]; b[1][1]=t[3];
            ldsm4(t, bBase + bOffH + 2u*16*LDT);  b[2][0]=t[0]; b[2][1]=t[1]; b[3][0]=t[2]; b[3][1]=t[3];
        }
#pragma unroll
        for (int mi = 0; mi < 4; mi++) ldsm4(a[mi], aBase + aOffH + 2u*(uint32_t)(mi*16)*LDT);
#pragma unroll
        for (int mi = 0; mi < 4; mi++)
#pragma unroll
            for (int nj = 0; nj < 4; nj++) mma16816(acc[mi][nj], a[mi], b[nj]);

        // pass 2: lo*hi
#pragma unroll
        for (int mi = 0; mi < 4; mi++) ldsm4(a[mi], aBase + aOffL + 2u*(uint32_t)(mi*16)*LDT);
#pragma unroll
        for (int mi = 0; mi < 4; mi++)
#pragma unroll
            for (int nj = 0; nj < 4; nj++) mma16816(acc[mi][nj], a[mi], b[nj]);

        // pass 3: hi*lo
        {
            uint32_t t[4];
            ldsm4(t, bBase + bOffL);              b[0][0]=t[0]; b[0][1]=t[1]; b[1][0]=t[2]; b[1][1]=t[3];
            ldsm4(t, bBase + bOffL + 2u*16*LDT);  b[2][0]=t[0]; b[2][1]=t[1]; b[3][0]=t[2]; b[3][1]=t[3];
        }
#pragma unroll
        for (int mi = 0; mi < 4; mi++) ldsm4(a[mi], aBase + aOffH + 2u*(uint32_t)(mi*16)*LDT);
#pragma unroll
        for (int mi = 0; mi < 4; mi++)
#pragma unroll
            for (int nj = 0; nj < 4; nj++) mma16816(acc[mi][nj], a[mi], b[nj]);

        if (pf) {
            int ns = st ^ 1;
            uint32_t hA[4], lA[4], hB[4], lB[4];
#pragma unroll
            for (int p = 0; p < 4; p++) { hA[p] = pack2(xa[2*p], xa[2*p+1], lA[p]); hB[p] = pack2(xb[2*p], xb[2*p+1], lB[p]); }
            *(uint4*)&As[ns][0][r][half*8] = make_uint4(hA[0],hA[1],hA[2],hA[3]);
            *(uint4*)&As[ns][1][r][half*8] = make_uint4(lA[0],lA[1],lA[2],lA[3]);
            *(uint4*)&Bs[ns][0][r][half*8] = make_uint4(hB[0],hB[1],hB[2],hB[3]);
            *(uint4*)&Bs[ns][1][r][half*8] = make_uint4(lB[0],lB[1],lB[2],lB[3]);
        }
        __syncthreads();
        st ^= 1;
    }

    // ---- epilogue ----
    int er = lane >> 2, ec = (lane & 3) * 2;
#pragma unroll
    for (int mi = 0; mi < 4; mi++)
#pragma unroll
        for (int nj = 0; nj < 4; nj++) {
            long row = (long)bm*128 + m0w + mi*16 + er;
            int  col = bn*128 + n0w + nj*8 + ec;
            float* p0 = &C[row*ldc + col];
            float* p1 = &C[(row+8)*ldc + col];
            float c0 = acc[mi][nj][0], c1 = acc[mi][nj][1];
            float c2 = acc[mi][nj][2], c3 = acc[mi][nj][3];
            if (mode == 2) {
                atomicAdd(p0,   0.25f*c0); atomicAdd(p0+1, 0.25f*c1);
                atomicAdd(p1,   0.25f*c2); atomicAdd(p1+1, 0.25f*c3);
            } else {
                if (mode == 1) { float b0 = bias[col], b1 = bias[col+1];
                                 c0 += b0; c1 += b1; c2 += b0; c3 += b1; }
                *(float2*)p0 = make_float2(c0, c1);
                *(float2*)p1 = make_float2(c2, c3);
            }
        }
}

// generic batched wrapper (z -> (b,h) via strides); causal skip / k trim / mode
__global__ void __launch_bounds__(256) gemm3(
    const float* __restrict__ A, const float* __restrict__ Bm,
    float* __restrict__ C, const float* __restrict__ bias,
    int K, int lda, int ldb, int ldc,
    long aSB, long aSH, long bSB, long bSH, long cSB, long cSH,
    int causal, int trim, int mode)
{
    int z = blockIdx.z;
    int bm = blockIdx.y, bn = blockIdx.x;
    if (causal && bn > bm) return;
    int kEnd = trim ? min(K, (bm+1)*128) : K;
    gemm3_body(A + (long)(z>>2)*aSB + (long)(z&3)*aSH,
               Bm + (long)(z>>2)*bSB + (long)(z&3)*bSH,
               C + (long)(z>>2)*cSB + (long)(z&3)*cSH,
               bias, kEnd, lda, ldb, ldc, bm, bn, mode);
}

// fused Q/K/V projections: z selects weight + destination
__global__ void __launch_bounds__(256) gemm3_qkv(
    const float* __restrict__ X,
    const float* __restrict__ Wq, const float* __restrict__ Wk, const float* __restrict__ Wv,
    float* __restrict__ Q, float* __restrict__ K, float* __restrict__ V)
{
    int w = blockIdx.z;
    const float* Bm = (w == 0) ? Wq : (w == 1) ? Wk : Wv;
    float* C        = (w == 0) ? Q  : (w == 1) ? K  : V;
    gemm3_body(X, Bm, C, nullptr, 1024, 1024, 1024, 1024, blockIdx.y, blockIdx.x, 0);
}

// ===========================================================================
// transposes (32x32 smem tiles)
// ===========================================================================
// V[b*2048+s][h*256+d] -> VT[(b*4+h)][d][s]
__global__ void __launch_bounds__(256) trans_bh(const float* __restrict__ src,
                                               float* __restrict__ dst)
{
    __shared__ float t[32][33];
    int z = blockIdx.z, b = z >> 2, h = z & 3;
    int s0 = blockIdx.x*32, d0 = blockIdx.y*32;
    int tx = threadIdx.x, ty = threadIdx.y;
    for (int i = ty; i < 32; i += 8)
        t[i][tx] = src[(long)(b*2048 + s0 + i)*1024 + h*256 + d0 + tx];
    __syncthreads();
    for (int i = ty; i < 32; i += 8)
        dst[((long)z*256 + d0 + i)*2048 + s0 + tx] = t[tx][i];
}

// X[r][h*256+d] -> XT[h][d][r], r over 8192
__global__ void __launch_bounds__(256) trans_h(const float* __restrict__ src,
                                              float* __restrict__ dst)
{
    __shared__ float t[32][33];
    int h = blockIdx.z;
    int r0 = blockIdx.x*32, d0 = blockIdx.y*32;
    int tx = threadIdx.x, ty = threadIdx.y;
    for (int i = ty; i < 32; i += 8)
        t[i][tx] = src[(long)(r0 + i)*1024 + h*256 + d0 + tx];
    __syncthreads();
    for (int i = ty; i < 32; i += 8)
        dst[((long)h*256 + d0 + i)*8192 + r0 + tx] = t[tx][i];
}

// ===========================================================================
// causal softmax (unchanged)
// ===========================================================================
__global__ void __launch_bounds__(256) softmax_causal(float* __restrict__ Sb)
{
    int row = blockIdx.x;
    int bh = row >> 11, i = row & 2047;
    float* p = Sb + (size_t)bh*Sq*Sq + (size_t)i*Sq;
    int n = i + 1;
    int tid = threadIdx.x;
    __shared__ float red[8];

    float m = -3.0e38f;
    for (int j = tid; j < n; j += 256) m = fmaxf(m, p[j]);
#pragma unroll
    for (int o = 16; o > 0; o >>= 1) m = fmaxf(m, __shfl_xor_sync(0xffffffffu, m, o));
    if ((tid & 31) == 0) red[tid >> 5] = m;
    __syncthreads();
    m = red[0];
#pragma unroll
    for (int w = 1; w < 8; w++) m = fmaxf(m, red[w]);
    __syncthreads();

    float s = 0.f;
    for (int j = tid; j < n; j += 256) { float e = __expf(p[j] - m); p[j] = e; s += e; }
#pragma unroll
    for (int o = 16; o > 0; o >>= 1) s += __shfl_xor_sync(0xffffffffu, s, o);
    if ((tid & 31) == 0) red[tid >> 5] = s;
    __syncthreads();
    s = red[0] + red[1] + red[2] + red[3] + red[4] + red[5] + red[6] + red[7];

    float inv = 1.f / s;
    for (int j = tid; j < n; j += 256) p[j] *= inv;
    for (int j = n + tid; j < Sq; j += 256) p[j] = 0.f;
}

// ===========================================================================
// A_mem / delta path (unchanged)
// ===========================================================================
__global__ void __launch_bounds__(256) amem_kernel(
    const float* __restrict__ src, const float* __restrict__ aux,
    const float* __restrict__ mem, const float* __restrict__ zv,
    const float* __restrict__ betas,
    float* __restrict__ outp, float* __restrict__ skout, int mode)
{
    __shared__ float sq[16][260];
    __shared__ float zh[256];
    __shared__ float den[16];
    __shared__ float red[8];

    int h = blockIdx.y;
    long row0 = (long)blockIdx.x * 16;
    int tid = threadIdx.x;
    zh[tid] = zv[h*256 + tid];

#pragma unroll
    for (int r = 0; r < 16; r++) {
        long idx = (row0 + r)*Dq + h*256 + tid;
        float x = src[idx];
        float s = x > 0.f ? x + 1.f : __expf(x);
        sq[r][tid] = s;
        if (mode == 1) skout[idx] = s;
    }
    __syncthreads();

    for (int r = 0; r < 16; r++) {
        float v = sq[r][tid] * zh[tid];
#pragma unroll
        for (int o = 16; o > 0; o >>= 1) v += __shfl_xor_sync(0xffffffffu, v, o);
        if ((tid & 31) == 0) red[tid >> 5] = v;
        __syncthreads();
        if (tid == 0) {
            float t = red[0]+red[1]+red[2]+red[3]+red[4]+red[5]+red[6]+red[7];
            den[r] = t + 1e-6f;
        }
        __syncthreads();
    }

    float acc[16] = {};
    const float* mh = mem + h*HDq*HDq;
    for (int d0 = 0; d0 < 256; d0 += 4) {
        float m0 = mh[(d0+0)*256 + tid];
        float m1 = mh[(d0+1)*256 + tid];
        float m2 = mh[(d0+2)*256 + tid];
        float m3 = mh[(d0+3)*256 + tid];
#pragma unroll
        for (int r = 0; r < 16; r++) {
            float4 sv = *(const float4*)&sq[r][d0];
            acc[r] += sv.x*m0 + sv.y*m1 + sv.z*m2 + sv.w*m3;
        }
    }

    if (mode == 0) {
        float g = 1.f / (1.f + __expf(-betas[h]));
        float og = 1.f - g;
#pragma unroll
        for (int r = 0; r < 16; r++) {
            long idx = (row0 + r)*Dq + h*256 + tid;
            outp[idx] = g*(acc[r]/den[r]) + og*aux[idx];
        }
    } else {
#pragma unroll
        for (int r = 0; r < 16; r++) {
            long idx = (row0 + r)*Dq + h*256 + tid;
            outp[idx] = aux[idx] - acc[r]/den[r];
        }
    }
}

__global__ void __launch_bounds__(256) init_state(
    const float* __restrict__ mem, const float* __restrict__ zv,
    float* __restrict__ out_mem, float* __restrict__ out_z)
{
    int i = blockIdx.x*256 + threadIdx.x;
    if (i < Hq*HDq*HDq) out_mem[i] = mem[i];
    if (i < Hq*HDq)     out_z[i]   = zv[i];
}

__global__ void __launch_bounds__(256) zsum_kernel(
    const float* __restrict__ SKb, float* __restrict__ outz)
{
    int col = blockIdx.x*256 + threadIdx.x;
    long r0 = (long)blockIdx.y * 512;
    float s = 0.f;
#pragma unroll 4
    for (int r = 0; r < 512; r++) s += SKb[(r0 + r)*Dq + col];
    atomicAdd(&outz[col], 0.25f*s);
}

// ---------------------------------------------------------------------------
extern "C" void kernel_launch(void* const* d_in, const int* in_sizes, int n_in,
                              void* d_out, int out_size)
{
    const float* X     = (const float*)d_in[0];
    const float* Wq    = (const float*)d_in[1];
    const float* Wk    = (const float*)d_in[2];
    const float* Wv    = (const float*)d_in[3];
    const float* Wo    = (const float*)d_in[4];
    const float* bo    = (const float*)d_in[5];
    const float* betas = (const float*)d_in[6];
    const float* mem   = (const float*)d_in[7];
    const float* zv    = (const float*)d_in[8];
    float* out = (float*)d_out;

    float *Q, *K, *V, *O, *BL, *SK, *VP, *Sc, *VT, *SKT, *VPT;
    cudaGetSymbolAddress((void**)&Q,   g_Q);
    cudaGetSymbolAddress((void**)&K,   g_K);
    cudaGetSymbolAddress((void**)&V,   g_V);
    cudaGetSymbolAddress((void**)&O,   g_O);
    cudaGetSymbolAddress((void**)&BL,  g_BL);
    cudaGetSymbolAddress((void**)&SK,  g_SK);
    cudaGetSymbolAddress((void**)&VP,  g_VP);
    cudaGetSymbolAddress((void**)&Sc,  g_S);
    cudaGetSymbolAddress((void**)&VT,  g_VT);
    cudaGetSymbolAddress((void**)&SKT, g_SKT);
    cudaGetSymbolAddress((void**)&VPT, g_VPT);

    const long OUT_MEM = (long)ROWSq*Dq;
    const long OUT_Z   = OUT_MEM + Hq*HDq*HDq;

    dim3 thr(256);
    dim3 tthr(32, 8);

    // 1. fused Q/K/V projections (bf16x3 tensor cores)
    gemm3_qkv<<<dim3(8,64,3), thr>>>(X, Wq, Wk, Wv, Q, K, V);

    // 2. V -> VT (per b,h)
    trans_bh<<<dim3(64,8,16), tthr>>>(V, VT);

    // 3. scores: S[bh] = Q_bh @ K_bh^T (causal blocks only)
    gemm3<<<dim3(16,16,16), thr>>>(Q, K, Sc, nullptr, 256, 1024, 1024, 2048,
                                   2097152L,256L, 2097152L,256L,
                                   16777216L,4194304L, 1, 0, 0);

    // 4. causal softmax
    softmax_causal<<<32768, thr>>>(Sc);

    // 5. O[bh] = P_bh @ VT_bh^T (NT; k trimmed by causality)
    gemm3<<<dim3(2,16,16), thr>>>(Sc, VT, O, nullptr, 2048, 2048, 2048, 1024,
                                  16777216L,4194304L, 2097152L,524288L,
                                  2097152L,256L, 0, 1, 0);

    // 6. blend: BL = g*A_mem + (1-g)*O
    amem_kernel<<<dim3(512,4), thr>>>(Q, O, mem, zv, betas, BL, nullptr, 0);

    // 7. delta: VP = V - delta, SK = elu(K)+1
    amem_kernel<<<dim3(512,4), thr>>>(K, V, mem, zv, betas, VP, SK, 1);

    // 8. SK/VP -> head-major transposes
    trans_h<<<dim3(256,8,4), tthr>>>(SK, SKT);
    trans_h<<<dim3(256,8,4), tthr>>>(VP, VPT);

    // 9. state init, then accumulations
    init_state<<<1024, thr>>>(mem, zv, out + OUT_MEM, out + OUT_Z);
    // mem_new[h] += (1/B) SKT_h @ VPT_h^T; z = h*4+chunk, chunk = k offset
    gemm3<<<dim3(2,2,16), thr>>>(SKT, VPT, out + OUT_MEM, nullptr,
                                 2048, 8192, 8192, 256,
                                 2097152L,2048L, 2097152L,2048L,
                                 65536L,0L, 0, 0, 2);
    zsum_kernel<<<dim3(4,16), thr>>>(SK, out + OUT_Z);

    // 10. output projection: out = BL @ Wo^T + bo
    gemm3<<<dim3(8,64,1), thr>>>(BL, Wo, out, bo, 1024, 1024, 1024, 1024,
                                 0,0, 0,0, 0,0, 0, 0, 1);
}